// round 1
// baseline (speedup 1.0000x reference)
#include <cuda_runtime.h>
#include <math.h>
#include <stdint.h>

// Problem constants
#define BATCH 16
#define SEQ   1024
#define CDIM  512
#define HDIM  64         // head dim
#define SCALE 0.125f     // 1/sqrt(64)

// ---------------------------------------------------------------------------
// Scratch (device globals — no allocations allowed)
// ---------------------------------------------------------------------------
__device__ float g_xp    [BATCH*SEQ*CDIM];     // x + pos_emb
__device__ float g_qkv_h [BATCH*SEQ*768];      // hifi qkv
__device__ float g_ql    [BATCH*SEQ*256];      // lofi q
__device__ float g_kvl   [BATCH*SEQ*512];      // lofi kv
__device__ float g_hifi_o[BATCH*SEQ*256];
__device__ float g_lofi_o[BATCH*SEQ*256];
__device__ float g_y     [BATCH*SEQ*512];      // concat(hifi_proj, lofi_proj)
__device__ float g_qkv_m [BATCH*SEQ*1536];     // mha qkv
__device__ float g_mha_o [BATCH*SEQ*512];

// ---------------------------------------------------------------------------
// x + pos_emb (pos broadcast over batch)
// ---------------------------------------------------------------------------
__global__ __launch_bounds__(256) void add_pos_kernel(
    const float* __restrict__ x, const float* __restrict__ pos, float* __restrict__ xp)
{
    const int per_b4 = SEQ*CDIM/4;  // 131072
    int i = blockIdx.x * blockDim.x + threadIdx.x;   // float4 index, grid covers all
    float4 a = reinterpret_cast<const float4*>(x)[i];
    float4 p = reinterpret_cast<const float4*>(pos)[i % per_b4];
    a.x += p.x; a.y += p.y; a.z += p.z; a.w += p.w;
    reinterpret_cast<float4*>(xp)[i] = a;
}

// ---------------------------------------------------------------------------
// SGEMM: C[M,N] = A[M,K] @ W[K,N] (+bias). Row-major everywhere.
// 128x128 block, BK=8, 256 threads, 8x8 per-thread register tile.
// Requires: M%128==0, N%128==0, K%8==0, lda/ldc multiples of 4.
// ---------------------------------------------------------------------------
__global__ __launch_bounds__(256) void sgemm_kernel(
    const float* __restrict__ A, const float* __restrict__ W,
    const float* __restrict__ bias, float* __restrict__ C,
    int M, int N, int K, int lda, int ldc)
{
    __shared__ float As[8][128];   // transposed A tile
    __shared__ float Bs[8][128];

    const int tid  = threadIdx.x;
    const int row0 = blockIdx.y * 128;
    const int col0 = blockIdx.x * 128;
    const int trow = tid >> 4;           // 0..15
    const int tcol = tid & 15;           // 0..15
    const int aRow = tid >> 1;           // 0..127
    const int aCol = (tid & 1) * 4;      // 0 or 4
    const int bRow = tid >> 5;           // 0..7
    const int bCol = (tid & 31) * 4;     // 0..124

    const float* Ab = A + (size_t)row0 * lda;
    const float* Wb = W + col0;

    float acc[8][8];
    #pragma unroll
    for (int i = 0; i < 8; i++)
        #pragma unroll
        for (int j = 0; j < 8; j++) acc[i][j] = 0.f;

    for (int k0 = 0; k0 < K; k0 += 8) {
        float4 a4 = *reinterpret_cast<const float4*>(Ab + (size_t)aRow * lda + k0 + aCol);
        As[aCol+0][aRow] = a4.x;
        As[aCol+1][aRow] = a4.y;
        As[aCol+2][aRow] = a4.z;
        As[aCol+3][aRow] = a4.w;
        float4 b4 = *reinterpret_cast<const float4*>(Wb + (size_t)(k0 + bRow) * N + bCol);
        *reinterpret_cast<float4*>(&Bs[bRow][bCol]) = b4;
        __syncthreads();

        #pragma unroll
        for (int kk = 0; kk < 8; kk++) {
            float regM[8], regN[8];
            *reinterpret_cast<float4*>(&regM[0]) = *reinterpret_cast<float4*>(&As[kk][trow*8]);
            *reinterpret_cast<float4*>(&regM[4]) = *reinterpret_cast<float4*>(&As[kk][trow*8+4]);
            *reinterpret_cast<float4*>(&regN[0]) = *reinterpret_cast<float4*>(&Bs[kk][tcol*8]);
            *reinterpret_cast<float4*>(&regN[4]) = *reinterpret_cast<float4*>(&Bs[kk][tcol*8+4]);
            #pragma unroll
            for (int i = 0; i < 8; i++)
                #pragma unroll
                for (int j = 0; j < 8; j++)
                    acc[i][j] += regM[i] * regN[j];
        }
        __syncthreads();
    }

    #pragma unroll
    for (int i = 0; i < 8; i++) {
        size_t r = (size_t)(row0 + trow*8 + i);
        float* Crow = C + r * ldc + col0 + tcol*8;
        #pragma unroll
        for (int j = 0; j < 8; j++) {
            float v = acc[i][j];
            if (bias) v += bias[col0 + tcol*8 + j];
            Crow[j] = v;
        }
    }
}

// ---------------------------------------------------------------------------
// Hifi: 2x2 window attention. One warp per (b, window, head).
// qkv layout: g_qkv_h[(b*SEQ+n)*768 + {0,256,512} + head*64 + d]
// out: g_hifi_o[(b*SEQ+n)*256 + head*64 + d]
// ---------------------------------------------------------------------------
__global__ __launch_bounds__(128) void hifi_attn_kernel(
    const float* __restrict__ qkv, float* __restrict__ outp)
{
    const int warp = threadIdx.x >> 5;
    const int lane = threadIdx.x & 31;
    const int unit = blockIdx.x * 4 + warp;   // 0..16383
    const int head = unit & 3;
    const int g    = (unit >> 2) & 255;
    const int b    = unit >> 10;
    const int gi   = g >> 4, gj = g & 15;

    int n[4];
    #pragma unroll
    for (int t = 0; t < 4; t++)
        n[t] = (gi*2 + (t>>1)) * 32 + gj*2 + (t&1);

    float q[4][2], k[4][2], v[4][2];
    #pragma unroll
    for (int t = 0; t < 4; t++) {
        const float* p = qkv + (size_t)(b*SEQ + n[t]) * 768 + head*64;
        q[t][0] = p[lane];        q[t][1] = p[lane+32];
        k[t][0] = p[256+lane];    k[t][1] = p[256+lane+32];
        v[t][0] = p[512+lane];    v[t][1] = p[512+lane+32];
    }

    float s[4][4];
    #pragma unroll
    for (int t = 0; t < 4; t++)
        #pragma unroll
        for (int u = 0; u < 4; u++)
            s[t][u] = q[t][0]*k[u][0] + q[t][1]*k[u][1];

    #pragma unroll
    for (int off = 16; off >= 1; off >>= 1)
        #pragma unroll
        for (int t = 0; t < 4; t++)
            #pragma unroll
            for (int u = 0; u < 4; u++)
                s[t][u] += __shfl_xor_sync(0xffffffffu, s[t][u], off);

    #pragma unroll
    for (int t = 0; t < 4; t++) {
        float s0 = s[t][0]*SCALE, s1 = s[t][1]*SCALE, s2 = s[t][2]*SCALE, s3 = s[t][3]*SCALE;
        float mx = fmaxf(fmaxf(s0, s1), fmaxf(s2, s3));
        float e0 = __expf(s0-mx), e1 = __expf(s1-mx), e2 = __expf(s2-mx), e3 = __expf(s3-mx);
        float inv = 1.f / (e0+e1+e2+e3);
        e0 *= inv; e1 *= inv; e2 *= inv; e3 *= inv;
        float o0 = e0*v[0][0] + e1*v[1][0] + e2*v[2][0] + e3*v[3][0];
        float o1 = e0*v[0][1] + e1*v[1][1] + e2*v[2][1] + e3*v[3][1];
        float* op = outp + (size_t)(b*SEQ + n[t]) * 256 + head*64;
        op[lane]    = o0;
        op[lane+32] = o1;
    }
}

// ---------------------------------------------------------------------------
// Flash attention, fp32, head_dim=64, 64x64 tiles, 256 threads.
// Thread (ty,tx): q-rows ty*4..+3; for S: k-cols tx*4..+3; for O: dims tx*4..+3.
// Dynamic smem: Qs, Ks, VsT, Ps — each [64][68].
// Scale folded into Q load.
// ---------------------------------------------------------------------------
#define FP 68
#define FA_SMEM (4 * 64 * FP * (int)sizeof(float))

extern __shared__ float fa_smem[];

__global__ __launch_bounds__(256) void flash_kernel(
    const float* __restrict__ Qp, const float* __restrict__ Kp,
    const float* __restrict__ Vp, float* __restrict__ Op,
    int q_rs, int k_rs, int v_rs, int o_rs, int seq)
{
    float* Qs  = fa_smem;
    float* Ks  = Qs  + 64*FP;
    float* VsT = Ks  + 64*FP;
    float* Ps  = VsT + 64*FP;

    const int b = blockIdx.z, head = blockIdx.y, qt = blockIdx.x;
    const size_t bo = (size_t)b * seq;
    const float* qb = Qp + (bo + qt*64) * q_rs + head*64;
    const float* kb = Kp + bo * k_rs + head*64;
    const float* vb = Vp + bo * v_rs + head*64;
    float* ob       = Op + (bo + qt*64) * o_rs + head*64;

    const int tid = threadIdx.x;
    const int ty = tid >> 4, tx = tid & 15;
    const int qr0 = ty*4, kr0 = tx*4, d0 = tx*4;

    // load Q tile (scale folded in)
    for (int i = tid; i < 4096; i += 256) {
        int r = i >> 6, c = i & 63;
        Qs[r*FP + c] = qb[(size_t)r * q_rs + c] * SCALE;
    }

    float m[4], l[4], o[4][4];
    #pragma unroll
    for (int i = 0; i < 4; i++) {
        m[i] = -1e30f; l[i] = 0.f;
        #pragma unroll
        for (int d = 0; d < 4; d++) o[i][d] = 0.f;
    }

    const int ntiles = seq >> 6;
    for (int kt = 0; kt < ntiles; kt++) {
        __syncthreads();   // prev PV done (and Q load visible on first iter)
        const float* kbt = kb + (size_t)kt * 64 * k_rs;
        const float* vbt = vb + (size_t)kt * 64 * v_rs;
        for (int i = tid; i < 4096; i += 256) {
            int r = i >> 6, c = i & 63;
            Ks [r*FP + c] = kbt[(size_t)r * k_rs + c];
            VsT[c*FP + r] = vbt[(size_t)r * v_rs + c];
        }
        __syncthreads();

        // S = Q K^T  (4x4 per thread)
        float s[4][4];
        #pragma unroll
        for (int i = 0; i < 4; i++)
            #pragma unroll
            for (int j = 0; j < 4; j++) s[i][j] = 0.f;

        for (int k = 0; k < 64; k += 4) {
            float4 qv[4], kv[4];
            #pragma unroll
            for (int i = 0; i < 4; i++)
                qv[i] = *reinterpret_cast<float4*>(&Qs[(qr0+i)*FP + k]);
            #pragma unroll
            for (int j = 0; j < 4; j++)
                kv[j] = *reinterpret_cast<float4*>(&Ks[(kr0+j)*FP + k]);
            #pragma unroll
            for (int i = 0; i < 4; i++)
                #pragma unroll
                for (int j = 0; j < 4; j++)
                    s[i][j] += qv[i].x*kv[j].x + qv[i].y*kv[j].y
                             + qv[i].z*kv[j].z + qv[i].w*kv[j].w;
        }

        // online softmax (row groups = 16 lanes sharing ty)
        #pragma unroll
        for (int i = 0; i < 4; i++) {
            float mx = fmaxf(fmaxf(s[i][0], s[i][1]), fmaxf(s[i][2], s[i][3]));
            #pragma unroll
            for (int off = 8; off >= 1; off >>= 1)
                mx = fmaxf(mx, __shfl_xor_sync(0xffffffffu, mx, off));
            float mnew = fmaxf(m[i], mx);
            float corr = __expf(m[i] - mnew);
            float rs = 0.f;
            #pragma unroll
            for (int j = 0; j < 4; j++) {
                float p = __expf(s[i][j] - mnew);
                Ps[(qr0+i)*FP + kr0 + j] = p;
                rs += p;
            }
            #pragma unroll
            for (int off = 8; off >= 1; off >>= 1)
                rs += __shfl_xor_sync(0xffffffffu, rs, off);
            l[i] = l[i] * corr + rs;
            m[i] = mnew;
            #pragma unroll
            for (int d = 0; d < 4; d++) o[i][d] *= corr;
        }
        __syncthreads();

        // O += P @ V
        for (int k = 0; k < 64; k += 4) {
            float4 pv[4], vv[4];
            #pragma unroll
            for (int i = 0; i < 4; i++)
                pv[i] = *reinterpret_cast<float4*>(&Ps[(qr0+i)*FP + k]);
            #pragma unroll
            for (int d = 0; d < 4; d++)
                vv[d] = *reinterpret_cast<float4*>(&VsT[(d0+d)*FP + k]);
            #pragma unroll
            for (int i = 0; i < 4; i++)
                #pragma unroll
                for (int d = 0; d < 4; d++)
                    o[i][d] += pv[i].x*vv[d].x + pv[i].y*vv[d].y
                             + pv[i].z*vv[d].z + pv[i].w*vv[d].w;
        }
    }

    #pragma unroll
    for (int i = 0; i < 4; i++) {
        float inv = 1.f / l[i];
        float4 res = make_float4(o[i][0]*inv, o[i][1]*inv, o[i][2]*inv, o[i][3]*inv);
        *reinterpret_cast<float4*>(&ob[(size_t)(qr0+i) * o_rs + d0]) = res;
    }
}

// ---------------------------------------------------------------------------
// Launch
// ---------------------------------------------------------------------------
extern "C" void kernel_launch(void* const* d_in, const int* in_sizes, int n_in,
                              void* d_out, int out_size)
{
    const float* x         = (const float*)d_in[0];
    const float* pos_emb   = (const float*)d_in[1];
    const float* l_q_w     = (const float*)d_in[2];
    const float* l_kv_w    = (const float*)d_in[3];
    const float* l_proj_w  = (const float*)d_in[4];
    const float* l_proj_b  = (const float*)d_in[5];
    const float* h_qkv_w   = (const float*)d_in[6];
    const float* h_proj_w  = (const float*)d_in[7];
    const float* h_proj_b  = (const float*)d_in[8];
    const float* in_proj_w = (const float*)d_in[9];
    const float* in_proj_b = (const float*)d_in[10];
    const float* out_proj_w= (const float*)d_in[11];
    const float* out_proj_b= (const float*)d_in[12];
    float* out = (float*)d_out;

    float *xp, *qkvh, *ql, *kvl, *hifio, *lofio, *y, *qkvm, *mhao;
    cudaGetSymbolAddress((void**)&xp,    g_xp);
    cudaGetSymbolAddress((void**)&qkvh,  g_qkv_h);
    cudaGetSymbolAddress((void**)&ql,    g_ql);
    cudaGetSymbolAddress((void**)&kvl,   g_kvl);
    cudaGetSymbolAddress((void**)&hifio, g_hifi_o);
    cudaGetSymbolAddress((void**)&lofio, g_lofi_o);
    cudaGetSymbolAddress((void**)&y,     g_y);
    cudaGetSymbolAddress((void**)&qkvm,  g_qkv_m);
    cudaGetSymbolAddress((void**)&mhao,  g_mha_o);

    cudaFuncSetAttribute(flash_kernel, cudaFuncAttributeMaxDynamicSharedMemorySize, FA_SMEM);

    const int M = BATCH * SEQ;   // 16384

    // 1. positional encoding
    add_pos_kernel<<<(BATCH*SEQ*CDIM/4 + 255)/256, 256>>>(x, pos_emb, xp);

    // 2. projections off xp
    sgemm_kernel<<<dim3(768/128,  M/128), 256>>>(xp, h_qkv_w, nullptr, qkvh, M, 768, 512, 512, 768);
    sgemm_kernel<<<dim3(256/128,  M/128), 256>>>(xp, l_q_w,   nullptr, ql,   M, 256, 512, 512, 256);
    sgemm_kernel<<<dim3(512/128,  M/128), 256>>>(xp, l_kv_w,  nullptr, kvl,  M, 512, 512, 512, 512);

    // 3. attention branches
    hifi_attn_kernel<<<4096, 128>>>(qkvh, hifio);
    flash_kernel<<<dim3(SEQ/64, 4, BATCH), 256, FA_SMEM>>>(
        ql, kvl, kvl + 256, lofio, 256, 512, 512, 256, SEQ);

    // 4. branch projections into concat buffer y
    sgemm_kernel<<<dim3(256/128,  M/128), 256>>>(hifio, h_proj_w, h_proj_b, y,       M, 256, 256, 256, 512);
    sgemm_kernel<<<dim3(256/128,  M/128), 256>>>(lofio, l_proj_w, l_proj_b, y + 256, M, 256, 256, 256, 512);

    // 5. final MHA
    sgemm_kernel<<<dim3(1536/128, M/128), 256>>>(y, in_proj_w, in_proj_b, qkvm, M, 1536, 512, 512, 1536);
    flash_kernel<<<dim3(SEQ/64, 8, BATCH), 256, FA_SMEM>>>(
        qkvm, qkvm + 512, qkvm + 1024, mhao, 1536, 1536, 1536, 512, SEQ);
    sgemm_kernel<<<dim3(512/128,  M/128), 256>>>(mhao, out_proj_w, out_proj_b, out, M, 512, 512, 512, 512);
}